// round 10
// baseline (speedup 1.0000x reference)
#include <cuda_runtime.h>
#include <cuda_bf16.h>
#include <cstdint>

// Problem constants
#define TSTEPS 512
#define BB 64
#define II 128
#define HH 512
#define OO 128
#define KK 32
#define ZK 640
#define NBLK 136                // 128 gate blocks (12 cols) + 8 out blocks (16 cols)
#define CLUSTER 4
#define NCLUS (NBLK/CLUSTER)    // 34 cluster leaders in the global barrier
#define NTH 256
#define GT (NBLK*NTH)

// smem layout (bytes)
#define HSM_OFF   0             // h slice [512][64] f32 = 131072
#define XSM_OFF   131072        // gate: x slice [128][64] f32 = 32768
#define WG_OFF    163840        // gate weights [640][12] f32x2-dup = 61440
#define WO_OFF    131072        // out weights  [512][16] f32x2-dup = 65536 (overlaps xsm)
#define WD_OFF    225280        // frac-diff weights [4][32] f32 = 512
#define MBAR_OFF  225792        // 4 h mbars + 1 x mbar
#define SMEM_BYTES 225856

typedef unsigned long long ull;

// ------------- static device scratch (no allocations) -------------
__device__ __align__(16) float g_xT[TSTEPS*II*BB];   // inputs transposed: [t][k][b]
__device__ __align__(16) float g_zH[2*HH*BB];        // h double buffer: [par][h][b]
__device__ __align__(16) float g_ring[KK*HH*BB];     // last 32 cell states: [j][h][b]
__device__ unsigned g_cnt;                           // leader-barrier count (self-restoring)
__device__ volatile unsigned g_sense_v;              // leader-barrier sense (self-restoring)

// ------------- helpers -------------
__device__ __forceinline__ ull ffma2(ull a, ull b, ull c) {
    ull d;
    asm("fma.rn.f32x2 %0, %1, %2, %3;" : "=l"(d) : "l"(a), "l"(b), "l"(c));
    return d;
}
__device__ __forceinline__ ull dup2(float w) {
    unsigned u = __float_as_uint(w);
    return ((ull)u << 32) | (ull)u;
}
__device__ __forceinline__ float sigm(float x) { return 1.f / (1.f + __expf(-x)); }

__device__ __forceinline__ unsigned smem_u32(const void* p) {
    return (unsigned)__cvta_generic_to_shared(p);
}
__device__ __forceinline__ void mbar_init(unsigned mbar, unsigned cnt) {
    asm volatile("mbarrier.init.shared.b64 [%0], %1;" :: "r"(mbar), "r"(cnt) : "memory");
}
__device__ __forceinline__ void mbar_expect(unsigned mbar, unsigned bytes) {
    asm volatile("mbarrier.arrive.expect_tx.shared.b64 _, [%0], %1;"
                 :: "r"(mbar), "r"(bytes) : "memory");
}
__device__ __forceinline__ void bulk_g2s_mc(unsigned dst, const void* src,
                                            unsigned bytes, unsigned mbar,
                                            unsigned short mask) {
    asm volatile("cp.async.bulk.shared::cluster.global.mbarrier::complete_tx::bytes"
                 ".multicast::cluster [%0], [%1], %2, [%3], %4;"
                 :: "r"(dst), "l"(src), "r"(bytes), "r"(mbar), "h"(mask) : "memory");
}
__device__ __forceinline__ void mbar_wait(unsigned mbar, unsigned parity) {
    asm volatile(
        "{\n\t"
        ".reg .pred P;\n\t"
        "WAIT_%=:\n\t"
        "mbarrier.try_wait.parity.acquire.cta.shared::cta.b64 P, [%0], %1, 0x989680;\n\t"
        "@P bra.uni DONE_%=;\n\t"
        "bra.uni WAIT_%=;\n\t"
        "DONE_%=:\n\t"
        "}" :: "r"(mbar), "r"(parity) : "memory");
}

// Hierarchical full-rendezvous grid barrier.
//   1) HW cluster barrier collapses each 4-CTA cluster.
//   2) The 34 cluster-leader CTAs run the R5-proven atomic sense-reversing
//      barrier (nanosleep-backoff spin; no poll storm).
//   3) Second HW cluster barrier releases the peers.
// Called 514 times per launch (even) -> g_cnt/g_sense_v self-restore.
__device__ __forceinline__ void gridbar(unsigned n, int rank) {
    __threadfence();
    __syncthreads();
    asm volatile("barrier.cluster.arrive.aligned;" ::: "memory");
    asm volatile("barrier.cluster.wait.aligned;"   ::: "memory");
    if (rank == 0 && threadIdx.x == 0) {
        unsigned s = (~n) & 1u;
        if (atomicAdd(&g_cnt, 1u) == NCLUS - 1) {
            g_cnt = 0;
            __threadfence();
            g_sense_v = s;
        } else {
            while (g_sense_v != s) __nanosleep(32);
        }
        __threadfence();
    }
    __syncthreads();           // hold leader CTA until its tid0 is released
    asm volatile("barrier.cluster.arrive.aligned;" ::: "memory");
    asm volatile("barrier.cluster.wait.aligned;"   ::: "memory");
}

extern __shared__ char smem_raw[];

__global__ void __launch_bounds__(NTH, 1) __cluster_dims__(CLUSTER, 1, 1)
mlstm_kernel(const float* __restrict__ inputs,
             const float* __restrict__ W_i, const float* __restrict__ b_i,
             const float* __restrict__ W_o, const float* __restrict__ b_o,
             const float* __restrict__ W_c, const float* __restrict__ b_c,
             const float* __restrict__ W_out, const float* __restrict__ b_out,
             const float* __restrict__ d_values,
             float* __restrict__ out)
{
    float* hsm   = (float*)(smem_raw + HSM_OFF);    // [512][64]
    float* xsm   = (float*)(smem_raw + XSM_OFF);    // [128][64] (gate only)
    ull*   wsg   = (ull*)(smem_raw + WG_OFF);       // gate [640][12], k-permuted
    ull*   wso   = (ull*)(smem_raw + WO_OFF);       // out  [512][16]
    float* wd_sm = (float*)(smem_raw + WD_OFF);     // [4][32]
    ull*   redsm = (ull*)(smem_raw + HSM_OFF);      // reuse h region
    float* redf  = (float*)redsm;

    const unsigned hbar0 = smem_u32(smem_raw + MBAR_OFF);  // 4 mbars, 8B apart
    const unsigned xbar  = hbar0 + 32;

    const int tid  = threadIdx.x;
    const int blk  = blockIdx.x;
    const int gtid = blk * NTH + tid;
    const int lane = tid & 31;
    const int wid  = tid >> 5;
    const int rank = blk & (CLUSTER - 1);

    const bool isOut = (blk >= 128);
    const int h0  = blk * 4;                 // gate blocks: 4 h each
    const int oc0 = (blk - 128) * 16;        // out blocks: 16 cols each
    const int eh  = tid >> 6;                // elementwise hh (0..3)
    const int eb  = tid & 63;                // elementwise b

    // ---------------- init ----------------
    if (tid == 0) {
        for (int c = 0; c < 4; ++c) mbar_init(hbar0 + c * 8, 1);
        mbar_init(xbar, 1);
    }
    if (!isOut) {
        // gate weights, k-permuted: kp in [w*80,w*80+64) = h rows 128+w*64+i;
        //                           kp in [w*80+64,w*80+80) = x rows w*16+i.
        for (int idx = tid; idx < ZK * 12; idx += NTH) {
            int kp = idx / 12;
            int j  = idx - kp * 12;
            int w  = kp / 80, r = kp - w * 80;
            int k  = (r < 64) ? (128 + w * 64 + r) : (w * 16 + (r - 64));
            int hh = j / 3, g = j - hh * 3;
            const float* W = (g == 0) ? W_i : (g == 1) ? W_o : W_c;
            wsg[idx] = dup2(W[k * HH + h0 + hh]);
        }
        if (tid < 4) {
            float dv = 0.5f * sigm(d_values[h0 + tid]);
            float v = 1.f;
            for (int i = 0; i < KK; ++i) {
                v = v * ((float)i - dv) / ((float)i + 1.f);
                wd_sm[tid * KK + (KK - 1 - i)] = v;
            }
        }
    } else {
        for (int idx = tid; idx < HH * 16; idx += NTH) {
            int kp = idx >> 4;
            int j  = idx & 15;
            wso[idx] = dup2(W_out[kp * OO + oc0 + j]);
        }
    }
    float rbi = 0.f, rbo = 0.f, rbc = 0.f;
    if (!isOut) { rbi = b_i[h0 + eh]; rbo = b_o[h0 + eh]; rbc = b_c[h0 + eh]; }

    // Transpose inputs once: g_xT[t][k][b]
    for (int idx = gtid; idx < TSTEPS * II * BB; idx += GT) {
        int t = idx >> 13;
        int r = idx & 8191;
        int k = r & 127, b = r >> 7;
        g_xT[(size_t)t * 8192 + k * 64 + b] = inputs[((size_t)t * BB + b) * II + k];
    }
    for (int idx = gtid; idx < 2 * HH * BB; idx += GT) g_zH[idx] = 0.f;
    __syncthreads();
    unsigned barid = 0;
    gridbar(barid++, rank);

    // Prefetch x(0): 4-way cooperative multicast slices (gate clusters)
    if (!isOut && tid == 0) {
        mbar_expect(xbar, 32768);
        bulk_g2s_mc(smem_u32(xsm) + rank * 8192, g_xT + rank * 2048, 8192, xbar, 0xF);
    }

    unsigned hph = 0, xph = 0;
    float rv[KK];                 // register ring: rv[j] = c_{u-32+j}
    #pragma unroll
    for (int j = 0; j < KK; ++j) rv[j] = 0.f;

    // ---------------- main scan ----------------
    for (int u = 0; u <= TSTEPS; ++u) {
        const bool active = isOut ? (u >= 1) : (u < TSTEPS);

        // h broadcast: each CTA loads one 32KB slice of h(u-1), multicasts.
        // Reads buffer (u-1)&1: written at iter u-1 (zeros at u=0 from init).
        if (active && tid == 0) {
            #pragma unroll
            for (int c = 0; c < 4; ++c) mbar_expect(hbar0 + c * 8, 32768);
            bulk_g2s_mc(smem_u32(hsm) + rank * 32768,
                        g_zH + ((unsigned)(u - 1) & 1u) * 32768 + rank * 8192,
                        32768, hbar0 + rank * 8, 0xF);
        }

        if (active) {
            if (!isOut) {
                ull acc[12];
                #pragma unroll
                for (int j = 0; j < 12; ++j) acc[j] = 0ULL;
                // x part first (prefetched last iter)
                mbar_wait(xbar, xph);
                {
                    const float* zp = xsm + (wid * 16) * 64 + lane * 2;
                    const ulonglong2* wp = (const ulonglong2*)(wsg + (size_t)(wid * 80 + 64) * 12);
                    #pragma unroll 4
                    for (int i = 0; i < 16; ++i) {
                        ull z = *(const ull*)(zp + i * 64);
                        ulonglong2 w0 = wp[i*6+0], w1 = wp[i*6+1], w2 = wp[i*6+2];
                        acc[0] = ffma2(z, w0.x, acc[0]);  acc[1] = ffma2(z, w0.y, acc[1]);
                        acc[2] = ffma2(z, w1.x, acc[2]);  acc[3] = ffma2(z, w1.y, acc[3]);
                        acc[4] = ffma2(z, w2.x, acc[4]);  acc[5] = ffma2(z, w2.y, acc[5]);
                        ulonglong2 w3 = wp[i*6+3], w4 = wp[i*6+4], w5 = wp[i*6+5];
                        acc[6] = ffma2(z, w3.x, acc[6]);   acc[7]  = ffma2(z, w3.y, acc[7]);
                        acc[8] = ffma2(z, w4.x, acc[8]);   acc[9]  = ffma2(z, w4.y, acc[9]);
                        acc[10] = ffma2(z, w5.x, acc[10]); acc[11] = ffma2(z, w5.y, acc[11]);
                    }
                }
                // h part: wait only this warp-pair's slice
                mbar_wait(hbar0 + (wid >> 1) * 8, hph);
                {
                    const float* zp = hsm + (wid * 64) * 64 + lane * 2;
                    const ulonglong2* wp = (const ulonglong2*)(wsg + (size_t)(wid * 80) * 12);
                    #pragma unroll 4
                    for (int i = 0; i < 64; ++i) {
                        ull z = *(const ull*)(zp + i * 64);
                        ulonglong2 w0 = wp[i*6+0], w1 = wp[i*6+1], w2 = wp[i*6+2];
                        acc[0] = ffma2(z, w0.x, acc[0]);  acc[1] = ffma2(z, w0.y, acc[1]);
                        acc[2] = ffma2(z, w1.x, acc[2]);  acc[3] = ffma2(z, w1.y, acc[3]);
                        acc[4] = ffma2(z, w2.x, acc[4]);  acc[5] = ffma2(z, w2.y, acc[5]);
                        ulonglong2 w3 = wp[i*6+3], w4 = wp[i*6+4], w5 = wp[i*6+5];
                        acc[6] = ffma2(z, w3.x, acc[6]);   acc[7]  = ffma2(z, w3.y, acc[7]);
                        acc[8] = ffma2(z, w4.x, acc[8]);   acc[9]  = ffma2(z, w4.y, acc[9]);
                        acc[10] = ffma2(z, w5.x, acc[10]); acc[11] = ffma2(z, w5.y, acc[11]);
                    }
                }
                __syncthreads();   // readers done with hsm/xsm
                #pragma unroll
                for (int j = 0; j < 12; ++j)
                    redsm[(wid * 12 + j) * 32 + lane] = acc[j];
            } else {
                ull acc[16];
                #pragma unroll
                for (int j = 0; j < 16; ++j) acc[j] = 0ULL;
                mbar_wait(hbar0 + (wid >> 1) * 8, hph);
                const float* zp = hsm + (wid * 64) * 64 + lane * 2;
                const ulonglong2* wp = (const ulonglong2*)(wso + (size_t)(wid * 64) * 16);
                #pragma unroll 4
                for (int i = 0; i < 64; ++i) {
                    ull z = *(const ull*)(zp + i * 64);
                    #pragma unroll
                    for (int q = 0; q < 8; ++q) {
                        ulonglong2 w = wp[i * 8 + q];
                        acc[2*q]   = ffma2(z, w.x, acc[2*q]);
                        acc[2*q+1] = ffma2(z, w.y, acc[2*q+1]);
                    }
                }
                __syncthreads();
                #pragma unroll
                for (int j = 0; j < 16; ++j)
                    redsm[(wid * 16 + j) * 32 + lane] = acc[j];
            }
        } else {
            __syncthreads();
        }

        // Prefetch x(u+1) — overlaps reduce/elementwise/barrier.
        if (!isOut && (u + 1) < TSTEPS && tid == 0) {
            mbar_expect(xbar, 32768);
            bulk_g2s_mc(smem_u32(xsm) + rank * 8192,
                        g_xT + (size_t)(u + 1) * 8192 + rank * 2048, 8192, xbar, 0xF);
        }
        __syncthreads();

        if (active) {
            if (isOut) {
                // outputs for step u-1; thread covers 4 (col,b) cells
                #pragma unroll
                for (int q = 0; q < 4; ++q) {
                    int cix = tid + q * 256;
                    int j = cix >> 6, b = cix & 63;
                    int oc = oc0 + j;
                    float s = 0.f;
                    #pragma unroll
                    for (int w = 0; w < 8; ++w)
                        s += redf[(w * 16 + j) * 64 + b];
                    out[((size_t)(u - 1) * BB + b) * OO + oc] = s + b_out[oc];
                }
            } else {
                float pi = rbi, po = rbo, pc = rbc;
                #pragma unroll
                for (int w = 0; w < 8; ++w) {
                    int base = (w * 12 + eh * 3) * 64 + eb;
                    pi += redf[base];
                    po += redf[base + 64];
                    pc += redf[base + 128];
                }
                float iv = sigm(pi);
                float ov = sigm(po);
                float gv = tanhf(pc);
                int h = h0 + eh;
                float l0 = 0.f, l1 = 0.f, l2 = 0.f, l3 = 0.f;
                #pragma unroll
                for (int j = 0; j < KK; j += 4) {
                    l0 += wd_sm[eh * KK + j    ] * rv[j];
                    l1 += wd_sm[eh * KK + j + 1] * rv[j + 1];
                    l2 += wd_sm[eh * KK + j + 2] * rv[j + 2];
                    l3 += wd_sm[eh * KK + j + 3] * rv[j + 3];
                }
                float cc = iv * gv - ((l0 + l1) + (l2 + l3));
                float hn = ov * tanhf(cc);
                // shift register ring (values identical to the old gmem ring)
                #pragma unroll
                for (int j = 0; j < KK - 1; ++j) rv[j] = rv[j + 1];
                rv[KK - 1] = cc;
                if (u >= TSTEPS - KK)
                    g_ring[((u - (TSTEPS - KK)) << 15) + h * 64 + eb] = cc;
                g_zH[((unsigned)u & 1u) * 32768 + h * 64 + eb] = hn;
                if (u == TSTEPS - 1)
                    out[(size_t)TSTEPS * BB * OO + (size_t)eb * HH + h] = hn;  // h_last
                xph ^= 1;
            }
            hph ^= 1;
        }
        gridbar(barid++, rank);   // calls 2..514
    }

    // hc_last[j][b][h]: slot j holds c_{480+j}; ring writes fenced by loop barriers
    const size_t OFF_HC = (size_t)TSTEPS * BB * OO + (size_t)BB * HH;
    for (int idx = gtid; idx < KK * BB * HH; idx += GT) {
        int j = idx >> 15;
        int r = idx & 32767;
        int b = r >> 9, h = r & 511;
        out[OFF_HC + idx] = __ldcg(&g_ring[(j << 15) + h * 64 + b]);
    }
}

extern "C" void kernel_launch(void* const* d_in, const int* in_sizes, int n_in,
                              void* d_out, int out_size) {
    (void)in_sizes; (void)n_in; (void)out_size;
    const float* inputs   = (const float*)d_in[0];
    const float* W_i      = (const float*)d_in[1];
    const float* b_i      = (const float*)d_in[2];
    const float* W_o      = (const float*)d_in[3];
    const float* b_o      = (const float*)d_in[4];
    const float* W_c      = (const float*)d_in[5];
    const float* b_c      = (const float*)d_in[6];
    const float* W_out    = (const float*)d_in[7];
    const float* b_out    = (const float*)d_in[8];
    const float* d_values = (const float*)d_in[9];
    float* out = (float*)d_out;

    cudaFuncSetAttribute(mlstm_kernel, cudaFuncAttributeMaxDynamicSharedMemorySize, SMEM_BYTES);
    mlstm_kernel<<<NBLK, NTH, SMEM_BYTES>>>(inputs, W_i, b_i, W_o, b_o, W_c, b_c,
                                            W_out, b_out, d_values, out);
}

// round 11
// speedup vs baseline: 1.0511x; 1.0511x over previous
#include <cuda_runtime.h>
#include <cuda_bf16.h>
#include <cstdint>

// Problem constants
#define TSTEPS 512
#define BB 64
#define II 128
#define HH 512
#define OO 128
#define KK 32
#define ZK 640
#define NBLK 136                // 128 gate blocks (12 cols) + 8 out blocks (16 cols)
#define CLUSTER 4
#define NTH 256
#define GT (NBLK*NTH)
#define NLEAF 8                 // barrier tree leaves; 136/8 = 17 CTAs per leaf

// smem layout (bytes)
#define HSM_OFF   0             // h slice [512][64] f32 = 131072
#define XSM_OFF   131072        // gate: x slice [128][64] f32 = 32768
#define WG_OFF    163840        // gate weights [640][12] f32x2-dup = 61440
#define WO_OFF    131072        // out weights  [512][16] f32x2-dup = 65536 (overlaps xsm)
#define WD_OFF    225280        // frac-diff weights [4][32] f32 = 512
#define MBAR_OFF  225792        // 4 h mbars + 1 x mbar
#define SMEM_BYTES 225856

typedef unsigned long long ull;

// ------------- static device scratch (no allocations) -------------
__device__ __align__(16) float g_xT[TSTEPS*II*BB];   // inputs transposed: [t][k][b]
__device__ __align__(16) float g_zH[2*HH*BB];        // h double buffer: [par][h][b]
__device__ __align__(16) float g_ring[KK*HH*BB];     // last 32 cell states: [j][h][b]
__device__ __align__(16) unsigned g_leaf[NLEAF*32];  // leaf counters, 128B apart
__device__ unsigned g_root;                          // root counter
__device__ volatile unsigned g_sense_v;              // sense flag (self-restoring)

// ------------- helpers -------------
__device__ __forceinline__ ull ffma2(ull a, ull b, ull c) {
    ull d;
    asm("fma.rn.f32x2 %0, %1, %2, %3;" : "=l"(d) : "l"(a), "l"(b), "l"(c));
    return d;
}
__device__ __forceinline__ ull dup2(float w) {
    unsigned u = __float_as_uint(w);
    return ((ull)u << 32) | (ull)u;
}
__device__ __forceinline__ float sigm(float x) { return 1.f / (1.f + __expf(-x)); }

__device__ __forceinline__ unsigned smem_u32(const void* p) {
    return (unsigned)__cvta_generic_to_shared(p);
}
__device__ __forceinline__ void mbar_init(unsigned mbar, unsigned cnt) {
    asm volatile("mbarrier.init.shared.b64 [%0], %1;" :: "r"(mbar), "r"(cnt) : "memory");
}
__device__ __forceinline__ void mbar_expect(unsigned mbar, unsigned bytes) {
    asm volatile("mbarrier.arrive.expect_tx.shared.b64 _, [%0], %1;"
                 :: "r"(mbar), "r"(bytes) : "memory");
}
__device__ __forceinline__ void bulk_g2s_mc(unsigned dst, const void* src,
                                            unsigned bytes, unsigned mbar,
                                            unsigned short mask) {
    asm volatile("cp.async.bulk.shared::cluster.global.mbarrier::complete_tx::bytes"
                 ".multicast::cluster [%0], [%1], %2, [%3], %4;"
                 :: "r"(dst), "l"(src), "r"(bytes), "r"(mbar), "h"(mask) : "memory");
}
__device__ __forceinline__ void mbar_wait(unsigned mbar, unsigned parity) {
    asm volatile(
        "{\n\t"
        ".reg .pred P;\n\t"
        "WAIT_%=:\n\t"
        "mbarrier.try_wait.parity.acquire.cta.shared::cta.b64 P, [%0], %1, 0x989680;\n\t"
        "@P bra.uni DONE_%=;\n\t"
        "bra.uni WAIT_%=;\n\t"
        "DONE_%=:\n\t"
        "}" :: "r"(mbar), "r"(parity) : "memory");
}

// Two-level combining-tree grid barrier.
// Arrival: atomicAdd on leaf (blk&7; 17 CTAs/leaf, leaves in parallel L2 slices);
// last leaf arriver resets leaf and combines into the root; last root arriver
// resets root and flips the single sense flag. Release: everyone spins on that
// ONE flag with nanosleep backoff — exactly the R5-proven release (no poll storm).
// Called 514x per launch (even) -> sense flag self-restores; counters reset inline.
__device__ __forceinline__ void gridbar(unsigned n) {
    __threadfence();
    __syncthreads();
    if (threadIdx.x == 0) {
        unsigned s = (~n) & 1u;
        unsigned leaf = (unsigned)blockIdx.x & (NLEAF - 1u);
        if (atomicAdd(&g_leaf[leaf * 32], 1u) == 16u) {   // last of 17 at this leaf
            g_leaf[leaf * 32] = 0u;                       // no re-arrival until sense flips
            __threadfence();                              // order reset before release chain
            if (atomicAdd(&g_root, 1u) == NLEAF - 1u) {   // last leaf-winner
                g_root = 0u;
                __threadfence();
                g_sense_v = s;
            } else {
                while (g_sense_v != s) __nanosleep(32);
            }
        } else {
            while (g_sense_v != s) __nanosleep(32);
        }
        __threadfence();
    }
    __syncthreads();
}

extern __shared__ char smem_raw[];

__global__ void __launch_bounds__(NTH, 1) __cluster_dims__(CLUSTER, 1, 1)
mlstm_kernel(const float* __restrict__ inputs,
             const float* __restrict__ W_i, const float* __restrict__ b_i,
             const float* __restrict__ W_o, const float* __restrict__ b_o,
             const float* __restrict__ W_c, const float* __restrict__ b_c,
             const float* __restrict__ W_out, const float* __restrict__ b_out,
             const float* __restrict__ d_values,
             float* __restrict__ out)
{
    float* hsm   = (float*)(smem_raw + HSM_OFF);    // [512][64]
    float* xsm   = (float*)(smem_raw + XSM_OFF);    // [128][64] (gate only)
    ull*   wsg   = (ull*)(smem_raw + WG_OFF);       // gate [640][12], k-permuted
    ull*   wso   = (ull*)(smem_raw + WO_OFF);       // out  [512][16]
    float* wd_sm = (float*)(smem_raw + WD_OFF);     // [4][32]
    ull*   redsm = (ull*)(smem_raw + HSM_OFF);      // reuse h region
    float* redf  = (float*)redsm;

    const unsigned hbar0 = smem_u32(smem_raw + MBAR_OFF);  // 4 mbars, 8B apart
    const unsigned xbar  = hbar0 + 32;

    const int tid  = threadIdx.x;
    const int blk  = blockIdx.x;
    const int gtid = blk * NTH + tid;
    const int lane = tid & 31;
    const int wid  = tid >> 5;
    const int rank = blk & (CLUSTER - 1);

    const bool isOut = (blk >= 128);
    const int h0  = blk * 4;                 // gate blocks: 4 h each
    const int oc0 = (blk - 128) * 16;        // out blocks: 16 cols each
    const int eh  = tid >> 6;                // elementwise hh (0..3)
    const int eb  = tid & 63;                // elementwise b

    // ---------------- init ----------------
    if (tid == 0) {
        for (int c = 0; c < 4; ++c) mbar_init(hbar0 + c * 8, 1);
        mbar_init(xbar, 1);
    }
    if (!isOut) {
        // gate weights, k-permuted: kp in [w*80,w*80+64) = h rows 128+w*64+i;
        //                           kp in [w*80+64,w*80+80) = x rows w*16+i.
        for (int idx = tid; idx < ZK * 12; idx += NTH) {
            int kp = idx / 12;
            int j  = idx - kp * 12;
            int w  = kp / 80, r = kp - w * 80;
            int k  = (r < 64) ? (128 + w * 64 + r) : (w * 16 + (r - 64));
            int hh = j / 3, g = j - hh * 3;
            const float* W = (g == 0) ? W_i : (g == 1) ? W_o : W_c;
            wsg[idx] = dup2(W[k * HH + h0 + hh]);
        }
        if (tid < 4) {
            float dv = 0.5f * sigm(d_values[h0 + tid]);
            float v = 1.f;
            for (int i = 0; i < KK; ++i) {
                v = v * ((float)i - dv) / ((float)i + 1.f);
                wd_sm[tid * KK + (KK - 1 - i)] = v;
            }
        }
    } else {
        for (int idx = tid; idx < HH * 16; idx += NTH) {
            int kp = idx >> 4;
            int j  = idx & 15;
            wso[idx] = dup2(W_out[kp * OO + oc0 + j]);
        }
    }
    float rbi = 0.f, rbo = 0.f, rbc = 0.f;
    if (!isOut) { rbi = b_i[h0 + eh]; rbo = b_o[h0 + eh]; rbc = b_c[h0 + eh]; }

    // Transpose inputs once: g_xT[t][k][b]
    for (int idx = gtid; idx < TSTEPS * II * BB; idx += GT) {
        int t = idx >> 13;
        int r = idx & 8191;
        int k = r & 127, b = r >> 7;
        g_xT[(size_t)t * 8192 + k * 64 + b] = inputs[((size_t)t * BB + b) * II + k];
    }
    for (int idx = gtid; idx < 2 * HH * BB; idx += GT) g_zH[idx] = 0.f;
    __syncthreads();
    unsigned barid = 0;
    gridbar(barid++);

    // Prefetch x(0): 4-way cooperative multicast slices (gate clusters)
    if (!isOut && tid == 0) {
        mbar_expect(xbar, 32768);
        bulk_g2s_mc(smem_u32(xsm) + rank * 8192, g_xT + rank * 2048, 8192, xbar, 0xF);
    }

    unsigned hph = 0, xph = 0;
    float rv[KK];                 // register ring: rv[j] = c_{u-32+j}
    #pragma unroll
    for (int j = 0; j < KK; ++j) rv[j] = 0.f;

    // ---------------- main scan ----------------
    for (int u = 0; u <= TSTEPS; ++u) {
        const bool active = isOut ? (u >= 1) : (u < TSTEPS);

        // h broadcast: each CTA loads one 32KB slice of h(u-1), multicasts.
        // Reads buffer (u-1)&1: written at iter u-1 (zeros at u=0 from init).
        if (active && tid == 0) {
            #pragma unroll
            for (int c = 0; c < 4; ++c) mbar_expect(hbar0 + c * 8, 32768);
            bulk_g2s_mc(smem_u32(hsm) + rank * 32768,
                        g_zH + ((unsigned)(u - 1) & 1u) * 32768 + rank * 8192,
                        32768, hbar0 + rank * 8, 0xF);
        }

        if (active) {
            if (!isOut) {
                ull acc[12];
                #pragma unroll
                for (int j = 0; j < 12; ++j) acc[j] = 0ULL;
                // x part first (prefetched last iter)
                mbar_wait(xbar, xph);
                {
                    const float* zp = xsm + (wid * 16) * 64 + lane * 2;
                    const ulonglong2* wp = (const ulonglong2*)(wsg + (size_t)(wid * 80 + 64) * 12);
                    #pragma unroll 4
                    for (int i = 0; i < 16; ++i) {
                        ull z = *(const ull*)(zp + i * 64);
                        ulonglong2 w0 = wp[i*6+0], w1 = wp[i*6+1], w2 = wp[i*6+2];
                        acc[0] = ffma2(z, w0.x, acc[0]);  acc[1] = ffma2(z, w0.y, acc[1]);
                        acc[2] = ffma2(z, w1.x, acc[2]);  acc[3] = ffma2(z, w1.y, acc[3]);
                        acc[4] = ffma2(z, w2.x, acc[4]);  acc[5] = ffma2(z, w2.y, acc[5]);
                        ulonglong2 w3 = wp[i*6+3], w4 = wp[i*6+4], w5 = wp[i*6+5];
                        acc[6] = ffma2(z, w3.x, acc[6]);   acc[7]  = ffma2(z, w3.y, acc[7]);
                        acc[8] = ffma2(z, w4.x, acc[8]);   acc[9]  = ffma2(z, w4.y, acc[9]);
                        acc[10] = ffma2(z, w5.x, acc[10]); acc[11] = ffma2(z, w5.y, acc[11]);
                    }
                }
                // h part: wait only this warp-pair's slice
                mbar_wait(hbar0 + (wid >> 1) * 8, hph);
                {
                    const float* zp = hsm + (wid * 64) * 64 + lane * 2;
                    const ulonglong2* wp = (const ulonglong2*)(wsg + (size_t)(wid * 80) * 12);
                    #pragma unroll 4
                    for (int i = 0; i < 64; ++i) {
                        ull z = *(const ull*)(zp + i * 64);
                        ulonglong2 w0 = wp[i*6+0], w1 = wp[i*6+1], w2 = wp[i*6+2];
                        acc[0] = ffma2(z, w0.x, acc[0]);  acc[1] = ffma2(z, w0.y, acc[1]);
                        acc[2] = ffma2(z, w1.x, acc[2]);  acc[3] = ffma2(z, w1.y, acc[3]);
                        acc[4] = ffma2(z, w2.x, acc[4]);  acc[5] = ffma2(z, w2.y, acc[5]);
                        ulonglong2 w3 = wp[i*6+3], w4 = wp[i*6+4], w5 = wp[i*6+5];
                        acc[6] = ffma2(z, w3.x, acc[6]);   acc[7]  = ffma2(z, w3.y, acc[7]);
                        acc[8] = ffma2(z, w4.x, acc[8]);   acc[9]  = ffma2(z, w4.y, acc[9]);
                        acc[10] = ffma2(z, w5.x, acc[10]); acc[11] = ffma2(z, w5.y, acc[11]);
                    }
                }
                __syncthreads();   // readers done with hsm/xsm
                #pragma unroll
                for (int j = 0; j < 12; ++j)
                    redsm[(wid * 12 + j) * 32 + lane] = acc[j];
            } else {
                ull acc[16];
                #pragma unroll
                for (int j = 0; j < 16; ++j) acc[j] = 0ULL;
                mbar_wait(hbar0 + (wid >> 1) * 8, hph);
                const float* zp = hsm + (wid * 64) * 64 + lane * 2;
                const ulonglong2* wp = (const ulonglong2*)(wso + (size_t)(wid * 64) * 16);
                #pragma unroll 4
                for (int i = 0; i < 64; ++i) {
                    ull z = *(const ull*)(zp + i * 64);
                    #pragma unroll
                    for (int q = 0; q < 8; ++q) {
                        ulonglong2 w = wp[i * 8 + q];
                        acc[2*q]   = ffma2(z, w.x, acc[2*q]);
                        acc[2*q+1] = ffma2(z, w.y, acc[2*q+1]);
                    }
                }
                __syncthreads();
                #pragma unroll
                for (int j = 0; j < 16; ++j)
                    redsm[(wid * 16 + j) * 32 + lane] = acc[j];
            }
        } else {
            __syncthreads();
        }

        // Prefetch x(u+1) — overlaps reduce/elementwise/barrier.
        if (!isOut && (u + 1) < TSTEPS && tid == 0) {
            mbar_expect(xbar, 32768);
            bulk_g2s_mc(smem_u32(xsm) + rank * 8192,
                        g_xT + (size_t)(u + 1) * 8192 + rank * 2048, 8192, xbar, 0xF);
        }
        __syncthreads();

        if (active) {
            if (isOut) {
                // outputs for step u-1; thread covers 4 (col,b) cells
                #pragma unroll
                for (int q = 0; q < 4; ++q) {
                    int cix = tid + q * 256;
                    int j = cix >> 6, b = cix & 63;
                    int oc = oc0 + j;
                    float s = 0.f;
                    #pragma unroll
                    for (int w = 0; w < 8; ++w)
                        s += redf[(w * 16 + j) * 64 + b];
                    out[((size_t)(u - 1) * BB + b) * OO + oc] = s + b_out[oc];
                }
            } else {
                float pi = rbi, po = rbo, pc = rbc;
                #pragma unroll
                for (int w = 0; w < 8; ++w) {
                    int base = (w * 12 + eh * 3) * 64 + eb;
                    pi += redf[base];
                    po += redf[base + 64];
                    pc += redf[base + 128];
                }
                float iv = sigm(pi);
                float ov = sigm(po);
                float gv = tanhf(pc);
                int h = h0 + eh;
                float l0 = 0.f, l1 = 0.f, l2 = 0.f, l3 = 0.f;
                #pragma unroll
                for (int j = 0; j < KK; j += 4) {
                    l0 += wd_sm[eh * KK + j    ] * rv[j];
                    l1 += wd_sm[eh * KK + j + 1] * rv[j + 1];
                    l2 += wd_sm[eh * KK + j + 2] * rv[j + 2];
                    l3 += wd_sm[eh * KK + j + 3] * rv[j + 3];
                }
                float cc = iv * gv - ((l0 + l1) + (l2 + l3));
                float hn = ov * tanhf(cc);
                // shift register ring (values identical to the old gmem ring)
                #pragma unroll
                for (int j = 0; j < KK - 1; ++j) rv[j] = rv[j + 1];
                rv[KK - 1] = cc;
                if (u >= TSTEPS - KK)
                    g_ring[((u - (TSTEPS - KK)) << 15) + h * 64 + eb] = cc;
                g_zH[((unsigned)u & 1u) * 32768 + h * 64 + eb] = hn;
                if (u == TSTEPS - 1)
                    out[(size_t)TSTEPS * BB * OO + (size_t)eb * HH + h] = hn;  // h_last
                xph ^= 1;
            }
            hph ^= 1;
        }
        gridbar(barid++);   // calls 2..514
    }

    // hc_last[j][b][h]: slot j holds c_{480+j}; ring writes fenced by loop barriers
    const size_t OFF_HC = (size_t)TSTEPS * BB * OO + (size_t)BB * HH;
    for (int idx = gtid; idx < KK * BB * HH; idx += GT) {
        int j = idx >> 15;
        int r = idx & 32767;
        int b = r >> 9, h = r & 511;
        out[OFF_HC + idx] = __ldcg(&g_ring[(j << 15) + h * 64 + b]);
    }
}

extern "C" void kernel_launch(void* const* d_in, const int* in_sizes, int n_in,
                              void* d_out, int out_size) {
    (void)in_sizes; (void)n_in; (void)out_size;
    const float* inputs   = (const float*)d_in[0];
    const float* W_i      = (const float*)d_in[1];
    const float* b_i      = (const float*)d_in[2];
    const float* W_o      = (const float*)d_in[3];
    const float* b_o      = (const float*)d_in[4];
    const float* W_c      = (const float*)d_in[5];
    const float* b_c      = (const float*)d_in[6];
    const float* W_out    = (const float*)d_in[7];
    const float* b_out    = (const float*)d_in[8];
    const float* d_values = (const float*)d_in[9];
    float* out = (float*)d_out;

    cudaFuncSetAttribute(mlstm_kernel, cudaFuncAttributeMaxDynamicSharedMemorySize, SMEM_BYTES);
    mlstm_kernel<<<NBLK, NTH, SMEM_BYTES>>>(inputs, W_i, b_i, W_o, b_o, W_c, b_c,
                                            W_out, b_out, d_values, out);
}

// round 12
// speedup vs baseline: 1.0971x; 1.0438x over previous
#include <cuda_runtime.h>
#include <cuda_bf16.h>
#include <cstdint>

// Problem constants
#define TSTEPS 512
#define BB 64
#define II 128
#define HH 512
#define OO 128
#define KK 32
#define ZK 640
#define NBLK 136                // 128 gate blocks (12 cols) + 8 out blocks (16 cols)
#define CLUSTER 4
#define NTH 256
#define GT (NBLK*NTH)

// smem layout (bytes)
#define HSM_OFF   0             // h slice [512][64] f32 = 131072
#define XSM_OFF   131072        // gate: x slice [128][64] f32 = 32768
#define WG_OFF    163840        // gate weights [640][12] f32x2-dup = 61440
#define WO_OFF    131072        // out weights  [512][16] f32x2-dup = 65536 (overlaps xsm)
#define WD_OFF    225280        // frac-diff weights [4][32] f32 = 512
#define MBAR_OFF  225792        // 4 h mbars + 1 x mbar
#define SMEM_BYTES 225856

typedef unsigned long long ull;

// ------------- static device scratch (no allocations) -------------
__device__ __align__(16) float g_xT[TSTEPS*II*BB];   // inputs transposed: [t][k][b]
__device__ __align__(16) float g_zH[2*HH*BB];        // h double buffer: [par][h][b]
__device__ __align__(16) float g_ring[KK*HH*BB];     // cell-state ring: [slot][h][b]
__device__ unsigned g_cnt;                           // barrier count (self-restoring)
__device__ volatile unsigned g_sense_v;              // barrier sense (self-restoring)

// ------------- helpers -------------
__device__ __forceinline__ ull ffma2(ull a, ull b, ull c) {
    ull d;
    asm("fma.rn.f32x2 %0, %1, %2, %3;" : "=l"(d) : "l"(a), "l"(b), "l"(c));
    return d;
}
__device__ __forceinline__ ull dup2(float w) {
    unsigned u = __float_as_uint(w);
    return ((ull)u << 32) | (ull)u;
}
__device__ __forceinline__ float sigm(float x) { return 1.f / (1.f + __expf(-x)); }

__device__ __forceinline__ unsigned smem_u32(const void* p) {
    return (unsigned)__cvta_generic_to_shared(p);
}
__device__ __forceinline__ void mbar_init(unsigned mbar, unsigned cnt) {
    asm volatile("mbarrier.init.shared.b64 [%0], %1;" :: "r"(mbar), "r"(cnt) : "memory");
}
__device__ __forceinline__ void mbar_expect(unsigned mbar, unsigned bytes) {
    asm volatile("mbarrier.arrive.expect_tx.shared.b64 _, [%0], %1;"
                 :: "r"(mbar), "r"(bytes) : "memory");
}
__device__ __forceinline__ void bulk_g2s_mc(unsigned dst, const void* src,
                                            unsigned bytes, unsigned mbar,
                                            unsigned short mask) {
    asm volatile("cp.async.bulk.shared::cluster.global.mbarrier::complete_tx::bytes"
                 ".multicast::cluster [%0], [%1], %2, [%3], %4;"
                 :: "r"(dst), "l"(src), "r"(bytes), "r"(mbar), "h"(mask) : "memory");
}
__device__ __forceinline__ void mbar_wait(unsigned mbar, unsigned parity) {
    asm volatile(
        "{\n\t"
        ".reg .pred P;\n\t"
        "WAIT_%=:\n\t"
        "mbarrier.try_wait.parity.acquire.cta.shared::cta.b64 P, [%0], %1, 0x989680;\n\t"
        "@P bra.uni DONE_%=;\n\t"
        "bra.uni WAIT_%=;\n\t"
        "DONE_%=:\n\t"
        "}" :: "r"(mbar), "r"(parity) : "memory");
}

// Champion serial sense-reversing grid barrier (best measured). 514 calls per
// launch (even) -> g_cnt/g_sense_v self-restore for graph replay.
__device__ __forceinline__ void gridbar(unsigned n) {
    __threadfence();
    __syncthreads();
    if (threadIdx.x == 0) {
        unsigned s = (~n) & 1u;
        if (atomicAdd(&g_cnt, 1u) == NBLK - 1) {
            g_cnt = 0;
            __threadfence();
            g_sense_v = s;
        } else {
            while (g_sense_v != s) __nanosleep(16);
        }
    }
    __syncthreads();
}

extern __shared__ char smem_raw[];

__global__ void __launch_bounds__(NTH, 1) __cluster_dims__(CLUSTER, 1, 1)
mlstm_kernel(const float* __restrict__ inputs,
             const float* __restrict__ W_i, const float* __restrict__ b_i,
             const float* __restrict__ W_o, const float* __restrict__ b_o,
             const float* __restrict__ W_c, const float* __restrict__ b_c,
             const float* __restrict__ W_out, const float* __restrict__ b_out,
             const float* __restrict__ d_values,
             float* __restrict__ out)
{
    float* hsm   = (float*)(smem_raw + HSM_OFF);    // [512][64]
    float* xsm   = (float*)(smem_raw + XSM_OFF);    // [128][64] (gate only)
    ull*   wsg   = (ull*)(smem_raw + WG_OFF);       // gate [640][12], k-permuted
    ull*   wso   = (ull*)(smem_raw + WO_OFF);       // out  [512][16]
    float* wd_sm = (float*)(smem_raw + WD_OFF);     // [4][32]
    ull*   redsm = (ull*)(smem_raw + HSM_OFF);      // reuse h region
    float* redf  = (float*)redsm;

    const unsigned hbar0 = smem_u32(smem_raw + MBAR_OFF);  // 4 mbars, 8B apart
    const unsigned xbar  = hbar0 + 32;

    const int tid  = threadIdx.x;
    const int blk  = blockIdx.x;
    const int gtid = blk * NTH + tid;
    const int lane = tid & 31;
    const int wid  = tid >> 5;
    const int rank = blk & (CLUSTER - 1);

    const bool isOut = (blk >= 128);
    const int h0  = blk * 4;                 // gate blocks: 4 h each
    const int oc0 = (blk - 128) * 16;        // out blocks: 16 cols each
    const int eh  = tid >> 6;                // elementwise hh (0..3)
    const int eb  = tid & 63;                // elementwise b

    // ---------------- init ----------------
    if (tid == 0) {
        for (int c = 0; c < 4; ++c) mbar_init(hbar0 + c * 8, 1);
        mbar_init(xbar, 1);
    }
    if (!isOut) {
        // gate weights, k-permuted: kp in [w*80,w*80+64) = h rows 128+w*64+i;
        //                           kp in [w*80+64,w*80+80) = x rows w*16+i.
        for (int idx = tid; idx < ZK * 12; idx += NTH) {
            int kp = idx / 12;
            int j  = idx - kp * 12;
            int w  = kp / 80, r = kp - w * 80;
            int k  = (r < 64) ? (128 + w * 64 + r) : (w * 16 + (r - 64));
            int hh = j / 3, g = j - hh * 3;
            const float* W = (g == 0) ? W_i : (g == 1) ? W_o : W_c;
            wsg[idx] = dup2(W[k * HH + h0 + hh]);
        }
        if (tid < 4) {
            float dv = 0.5f * sigm(d_values[h0 + tid]);
            float v = 1.f;
            for (int i = 0; i < KK; ++i) {
                v = v * ((float)i - dv) / ((float)i + 1.f);
                wd_sm[tid * KK + (KK - 1 - i)] = v;
            }
        }
    } else {
        for (int idx = tid; idx < HH * 16; idx += NTH) {
            int kp = idx >> 4;
            int j  = idx & 15;
            wso[idx] = dup2(W_out[kp * OO + oc0 + j]);
        }
    }
    float rbi = 0.f, rbo = 0.f, rbc = 0.f;
    if (!isOut) { rbi = b_i[h0 + eh]; rbo = b_o[h0 + eh]; rbc = b_c[h0 + eh]; }

    // Transpose inputs once: g_xT[t][k][b]
    for (int idx = gtid; idx < TSTEPS * II * BB; idx += GT) {
        int t = idx >> 13;
        int r = idx & 8191;
        int k = r & 127, b = r >> 7;
        g_xT[(size_t)t * 8192 + k * 64 + b] = inputs[((size_t)t * BB + b) * II + k];
    }
    for (int idx = gtid; idx < 2 * HH * BB; idx += GT) g_zH[idx] = 0.f;
    for (int idx = gtid; idx < KK * HH * BB; idx += GT) g_ring[idx] = 0.f;
    __syncthreads();
    unsigned barid = 0;
    gridbar(barid++);

    // Prefetch x(0): 4-way cooperative multicast slices (gate clusters)
    if (!isOut && tid == 0) {
        mbar_expect(xbar, 32768);
        bulk_g2s_mc(smem_u32(xsm) + rank * 8192, g_xT + rank * 2048, 8192, xbar, 0xF);
    }

    unsigned hph = 0, xph = 0;

    // ---------------- main scan ----------------
    for (int u = 0; u <= TSTEPS; ++u) {
        const bool active = isOut ? (u >= 1) : (u < TSTEPS);

        // h broadcast: each CTA loads one 32KB slice of h(u-1) from buffer
        // (u-1)&1 (zeros at u=0 from init), multicasts to its cluster.
        if (active && tid == 0) {
            #pragma unroll
            for (int c = 0; c < 4; ++c) mbar_expect(hbar0 + c * 8, 32768);
            bulk_g2s_mc(smem_u32(hsm) + rank * 32768,
                        g_zH + (((unsigned)(u - 1)) & 1u) * 32768 + rank * 8192,
                        32768, hbar0 + rank * 8, 0xF);
        }

        if (active) {
            if (!isOut) {
                ull acc[12];
                #pragma unroll
                for (int j = 0; j < 12; ++j) acc[j] = 0ULL;
                // x part first (prefetched last iter)
                mbar_wait(xbar, xph);
                {
                    const float* zp = xsm + (wid * 16) * 64 + lane * 2;
                    const ulonglong2* wp = (const ulonglong2*)(wsg + (size_t)(wid * 80 + 64) * 12);
                    #pragma unroll 4
                    for (int i = 0; i < 16; ++i) {
                        ull z = *(const ull*)(zp + i * 64);
                        ulonglong2 w0 = wp[i*6+0], w1 = wp[i*6+1], w2 = wp[i*6+2];
                        acc[0] = ffma2(z, w0.x, acc[0]);  acc[1] = ffma2(z, w0.y, acc[1]);
                        acc[2] = ffma2(z, w1.x, acc[2]);  acc[3] = ffma2(z, w1.y, acc[3]);
                        acc[4] = ffma2(z, w2.x, acc[4]);  acc[5] = ffma2(z, w2.y, acc[5]);
                        ulonglong2 w3 = wp[i*6+3], w4 = wp[i*6+4], w5 = wp[i*6+5];
                        acc[6] = ffma2(z, w3.x, acc[6]);   acc[7]  = ffma2(z, w3.y, acc[7]);
                        acc[8] = ffma2(z, w4.x, acc[8]);   acc[9]  = ffma2(z, w4.y, acc[9]);
                        acc[10] = ffma2(z, w5.x, acc[10]); acc[11] = ffma2(z, w5.y, acc[11]);
                    }
                }
                // h part: wait only this warp-pair's slice
                mbar_wait(hbar0 + (wid >> 1) * 8, hph);
                {
                    const float* zp = hsm + (wid * 64) * 64 + lane * 2;
                    const ulonglong2* wp = (const ulonglong2*)(wsg + (size_t)(wid * 80) * 12);
                    #pragma unroll 4
                    for (int i = 0; i < 64; ++i) {
                        ull z = *(const ull*)(zp + i * 64);
                        ulonglong2 w0 = wp[i*6+0], w1 = wp[i*6+1], w2 = wp[i*6+2];
                        acc[0] = ffma2(z, w0.x, acc[0]);  acc[1] = ffma2(z, w0.y, acc[1]);
                        acc[2] = ffma2(z, w1.x, acc[2]);  acc[3] = ffma2(z, w1.y, acc[3]);
                        acc[4] = ffma2(z, w2.x, acc[4]);  acc[5] = ffma2(z, w2.y, acc[5]);
                        ulonglong2 w3 = wp[i*6+3], w4 = wp[i*6+4], w5 = wp[i*6+5];
                        acc[6] = ffma2(z, w3.x, acc[6]);   acc[7]  = ffma2(z, w3.y, acc[7]);
                        acc[8] = ffma2(z, w4.x, acc[8]);   acc[9]  = ffma2(z, w4.y, acc[9]);
                        acc[10] = ffma2(z, w5.x, acc[10]); acc[11] = ffma2(z, w5.y, acc[11]);
                    }
                }
                __syncthreads();   // readers done with hsm/xsm
                #pragma unroll
                for (int j = 0; j < 12; ++j)
                    redsm[(wid * 12 + j) * 32 + lane] = acc[j];
            } else {
                ull acc[16];
                #pragma unroll
                for (int j = 0; j < 16; ++j) acc[j] = 0ULL;
                mbar_wait(hbar0 + (wid >> 1) * 8, hph);
                const float* zp = hsm + (wid * 64) * 64 + lane * 2;
                const ulonglong2* wp = (const ulonglong2*)(wso + (size_t)(wid * 64) * 16);
                #pragma unroll 4
                for (int i = 0; i < 64; ++i) {
                    ull z = *(const ull*)(zp + i * 64);
                    #pragma unroll
                    for (int q = 0; q < 8; ++q) {
                        ulonglong2 w = wp[i * 8 + q];
                        acc[2*q]   = ffma2(z, w.x, acc[2*q]);
                        acc[2*q+1] = ffma2(z, w.y, acc[2*q+1]);
                    }
                }
                __syncthreads();
                #pragma unroll
                for (int j = 0; j < 16; ++j)
                    redsm[(wid * 16 + j) * 32 + lane] = acc[j];
            }
        } else {
            __syncthreads();
        }

        // Prefetch x(u+1) — overlaps reduce/elementwise/barrier.
        if (!isOut && (u + 1) < TSTEPS && tid == 0) {
            mbar_expect(xbar, 32768);
            bulk_g2s_mc(smem_u32(xsm) + rank * 8192,
                        g_xT + (size_t)(u + 1) * 8192 + rank * 2048, 8192, xbar, 0xF);
        }
        __syncthreads();

        if (active) {
            if (isOut) {
                // outputs for step u-1; thread covers 4 (col,b) cells
                #pragma unroll
                for (int q = 0; q < 4; ++q) {
                    int cix = tid + q * 256;
                    int j = cix >> 6, b = cix & 63;
                    int oc = oc0 + j;
                    float s = 0.f;
                    #pragma unroll
                    for (int w = 0; w < 8; ++w)
                        s += redf[(w * 16 + j) * 64 + b];
                    out[((size_t)(u - 1) * BB + b) * OO + oc] = s + b_out[oc];
                }
            } else {
                float pi = rbi, po = rbo, pc = rbc;
                #pragma unroll
                for (int w = 0; w < 8; ++w) {
                    int base = (w * 12 + eh * 3) * 64 + eb;
                    pi += redf[base];
                    po += redf[base + 64];
                    pc += redf[base + 128];
                }
                float iv = sigm(pi);
                float ov = sigm(po);
                float gv = tanhf(pc);
                int h = h0 + eh;
                // lag = sum_j wd[j]*c_{u-K+j}; slot of c_{u-K+j} = (u+j)&31
                // (inline ring loads: champion pattern, keeps regs low in GEMM)
                float l0 = 0.f, l1 = 0.f, l2 = 0.f, l3 = 0.f;
                #pragma unroll
                for (int j = 0; j < KK; j += 4) {
                    int s0 = (u + j    ) & 31;
                    int s1 = (u + j + 1) & 31;
                    int s2 = (u + j + 2) & 31;
                    int s3 = (u + j + 3) & 31;
                    l0 += wd_sm[eh * KK + j    ] * __ldcg(&g_ring[(s0 << 15) + h * 64 + eb]);
                    l1 += wd_sm[eh * KK + j + 1] * __ldcg(&g_ring[(s1 << 15) + h * 64 + eb]);
                    l2 += wd_sm[eh * KK + j + 2] * __ldcg(&g_ring[(s2 << 15) + h * 64 + eb]);
                    l3 += wd_sm[eh * KK + j + 3] * __ldcg(&g_ring[(s3 << 15) + h * 64 + eb]);
                }
                float cc = iv * gv - ((l0 + l1) + (l2 + l3));
                float hn = ov * tanhf(cc);
                g_ring[((u & 31) << 15) + h * 64 + eb] = cc;
                g_zH[((unsigned)u & 1u) * 32768 + h * 64 + eb] = hn;
                if (u == TSTEPS - 1)
                    out[(size_t)TSTEPS * BB * OO + (size_t)eb * HH + h] = hn;  // h_last
                xph ^= 1;
            }
            hph ^= 1;
        }
        gridbar(barid++);   // calls 2..514
    }

    // hc_last[j][b][h]: slot j holds c_{480+j} (480 % 32 == 0)
    const size_t OFF_HC = (size_t)TSTEPS * BB * OO + (size_t)BB * HH;
    for (int idx = gtid; idx < KK * BB * HH; idx += GT) {
        int j = idx >> 15;
        int r = idx & 32767;
        int b = r >> 9, h = r & 511;
        out[OFF_HC + idx] = __ldcg(&g_ring[(j << 15) + h * 64 + b]);
    }
}

extern "C" void kernel_launch(void* const* d_in, const int* in_sizes, int n_in,
                              void* d_out, int out_size) {
    (void)in_sizes; (void)n_in; (void)out_size;
    const float* inputs   = (const float*)d_in[0];
    const float* W_i      = (const float*)d_in[1];
    const float* b_i      = (const float*)d_in[2];
    const float* W_o      = (const float*)d_in[3];
    const float* b_o      = (const float*)d_in[4];
    const float* W_c      = (const float*)d_in[5];
    const float* b_c      = (const float*)d_in[6];
    const float* W_out    = (const float*)d_in[7];
    const float* b_out    = (const float*)d_in[8];
    const float* d_values = (const float*)d_in[9];
    float* out = (float*)d_out;

    cudaFuncSetAttribute(mlstm_kernel, cudaFuncAttributeMaxDynamicSharedMemorySize, SMEM_BYTES);
    mlstm_kernel<<<NBLK, NTH, SMEM_BYTES>>>(inputs, W_i, b_i, W_o, b_o, W_c, b_c,
                                            W_out, b_out, d_values, out);
}

// round 13
// speedup vs baseline: 1.2109x; 1.1037x over previous
#include <cuda_runtime.h>
#include <cuda_bf16.h>
#include <cstdint>

// Problem constants
#define TSTEPS 512
#define BB 64
#define II 128
#define HH 512
#define OO 128
#define KK 32
#define ZK 640                  // I + H
#define NBLK 139                // 128 gate blocks + 11 out blocks
#define NTH 256
#define GT (NBLK*NTH)

// smem layout (bytes)
#define HSM_OFF   0             // h slice [512][64] f32 = 131072
#define XSM_OFF   131072        // x slice [128][64] f32 = 32768
#define WSM_OFF   163840        // weights [640][12] f32x2-dup = 61440
#define WD_OFF    225280        // frac-diff weights [4][32] f32 = 512
#define MBAR_OFF  225792        // 4 h mbars + 1 x mbar (8B each)
#define SMEM_BYTES (MBAR_OFF + 64)

typedef unsigned long long ull;

// ------------- static device scratch (no allocations) -------------
__device__ float g_xT[TSTEPS*II*BB];     // inputs transposed: [t][k][b]
__device__ float g_zH[HH*BB];            // h_{t-1}: [h][b]
__device__ float g_ring[KK*HH*BB];       // last 32 cell states: [j][h][b]
__device__ unsigned g_cnt;
__device__ volatile unsigned g_sense_v;

// ------------- helpers -------------
__device__ __forceinline__ ull ffma2(ull a, ull b, ull c) {
    ull d;
    asm("fma.rn.f32x2 %0, %1, %2, %3;" : "=l"(d) : "l"(a), "l"(b), "l"(c));
    return d;
}
__device__ __forceinline__ ull dup2(float w) {
    unsigned u = __float_as_uint(w);
    return ((ull)u << 32) | (ull)u;
}
__device__ __forceinline__ float sigm(float x) { return 1.f / (1.f + __expf(-x)); }

__device__ __forceinline__ unsigned smem_u32(const void* p) {
    return (unsigned)__cvta_generic_to_shared(p);
}
__device__ __forceinline__ void mbar_init(unsigned mbar, unsigned cnt) {
    asm volatile("mbarrier.init.shared.b64 [%0], %1;" :: "r"(mbar), "r"(cnt) : "memory");
}
__device__ __forceinline__ void mbar_expect(unsigned mbar, unsigned bytes) {
    asm volatile("mbarrier.arrive.expect_tx.shared.b64 _, [%0], %1;"
                 :: "r"(mbar), "r"(bytes) : "memory");
}
__device__ __forceinline__ void bulk_g2s(unsigned dst, const void* src,
                                         unsigned bytes, unsigned mbar) {
    asm volatile("cp.async.bulk.shared::cluster.global.mbarrier::complete_tx::bytes "
                 "[%0], [%1], %2, [%3];"
                 :: "r"(dst), "l"(src), "r"(bytes), "r"(mbar) : "memory");
}
__device__ __forceinline__ void mbar_wait(unsigned mbar, unsigned parity) {
    asm volatile(
        "{\n\t"
        ".reg .pred P;\n\t"
        "WAIT_%=:\n\t"
        "mbarrier.try_wait.parity.acquire.cta.shared::cta.b64 P, [%0], %1, 0x989680;\n\t"
        "@P bra.uni DONE_%=;\n\t"
        "bra.uni WAIT_%=;\n\t"
        "DONE_%=:\n\t"
        "}" :: "r"(mbar), "r"(parity) : "memory");
}

// Champion serial sense-reversing grid barrier; state self-restores (even calls).
__device__ __forceinline__ void gridbar(unsigned n) {
    __threadfence();
    __syncthreads();
    if (threadIdx.x == 0) {
        unsigned s = (~n) & 1u;
        if (atomicAdd(&g_cnt, 1u) == NBLK - 1) {
            g_cnt = 0;
            __threadfence();
            g_sense_v = s;
        } else {
            while (g_sense_v != s) __nanosleep(16);
        }
    }
    __syncthreads();
}

extern __shared__ char smem_raw[];

__global__ void __launch_bounds__(NTH, 1)
mlstm_kernel(const float* __restrict__ inputs,
             const float* __restrict__ W_i, const float* __restrict__ b_i,
             const float* __restrict__ W_o, const float* __restrict__ b_o,
             const float* __restrict__ W_c, const float* __restrict__ b_c,
             const float* __restrict__ W_out, const float* __restrict__ b_out,
             const float* __restrict__ d_values,
             float* __restrict__ out)
{
    float* hsm   = (float*)(smem_raw + HSM_OFF);    // [512][64]
    float* xsm   = (float*)(smem_raw + XSM_OFF);    // [128][64]
    ull*   wsm   = (ull*)(smem_raw + WSM_OFF);      // [640][12] permuted k
    float* wd_sm = (float*)(smem_raw + WD_OFF);     // [4][32]
    ull*   redsm = (ull*)(smem_raw + HSM_OFF);      // reuse h region: [8][12][32]
    float* redf  = (float*)redsm;

    const unsigned hbar0 = smem_u32(smem_raw + MBAR_OFF);  // 4 mbars, 8B apart
    const unsigned xbar  = hbar0 + 32;

    const int tid  = threadIdx.x;
    const int blk  = blockIdx.x;
    const int gtid = blk * NTH + tid;
    const int lane = tid & 31;
    const int wid  = tid >> 5;

    const bool isOut = (blk >= 128);
    const int h0  = blk * 4;                 // gate blocks: 4 h each
    const int oc0 = (blk - 128) * 12;        // out blocks
    const int ncols = isOut ? ((128 - oc0) < 12 ? (128 - oc0) : 12) : 12;
    const int eh  = tid >> 6;                // elementwise hh (0..3)
    const int eb  = tid & 63;                // elementwise b

    // ---------------- init ----------------
    if (tid == 0) {
        for (int c = 0; c < 4; ++c) mbar_init(hbar0 + c * 8, 1);
        mbar_init(xbar, 1);
    }
    // Weights -> smem, k-permuted: storage kp for warp w: [w*80, w*80+64) are
    // h-rows 128+w*64+i ; [w*80+64, w*80+80) are x-rows w*16+i.
    for (int idx = tid; idx < ZK * 12; idx += NTH) {
        int kp = idx / 12;
        int j  = idx - kp * 12;
        int w  = kp / 80, r = kp - w * 80;
        int k  = (r < 64) ? (128 + w * 64 + r) : (w * 16 + (r - 64));
        float wv = 0.f;
        if (!isOut) {
            int hh = j / 3, g = j - hh * 3;
            const float* W = (g == 0) ? W_i : (g == 1) ? W_o : W_c;
            wv = W[k * HH + h0 + hh];
        } else if ((oc0 + j) < OO && k >= II) {
            wv = W_out[(k - II) * OO + oc0 + j];
        }
        wsm[idx] = dup2(wv);
    }
    float rbi = 0.f, rbo = 0.f, rbc = 0.f;
    if (!isOut) {
        if (tid < 4) {
            float dv = 0.5f * sigm(d_values[h0 + tid]);
            float v = 1.f;
            for (int i = 0; i < KK; ++i) {
                v = v * ((float)i - dv) / ((float)i + 1.f);
                wd_sm[tid * KK + (KK - 1 - i)] = v;
            }
        }
        rbi = b_i[h0 + eh]; rbo = b_o[h0 + eh]; rbc = b_c[h0 + eh];
    }
    // Transpose inputs once: g_xT[t][k][b]
    for (int idx = gtid; idx < TSTEPS * II * BB; idx += GT) {
        int t = idx >> 13;
        int r = idx & 8191;
        int k = r & 127, b = r >> 7;
        g_xT[(size_t)t * 8192 + k * 64 + b] = inputs[((size_t)t * BB + b) * II + k];
    }
    for (int idx = gtid; idx < HH * BB; idx += GT) g_zH[idx] = 0.f;
    for (int idx = gtid; idx < KK * HH * BB; idx += GT) g_ring[idx] = 0.f;
    __syncthreads();
    unsigned barid = 0;
    gridbar(barid++);

    // Prefetch x(0) (gate blocks only)
    if (!isOut && tid == 0) {
        mbar_expect(xbar, 32768);
        bulk_g2s(smem_u32(xsm), g_xT, 32768, xbar);
    }

    unsigned hph = 0, xph = 0;
    float rv[KK];                 // register shift-ring: rv[j] = c_{u-32+j}
    #pragma unroll
    for (int j = 0; j < KK; ++j) rv[j] = 0.f;

    // ---------------- main scan ----------------
    for (int u = 0; u <= TSTEPS; ++u) {
        const bool active = isOut ? (u >= 1) : (u < TSTEPS);

        // h DMA: each CTA pulls all four 32KB slices itself (champion pattern:
        // no cross-CTA issue coupling; L2 bandwidth is not the binding item).
        if (active && tid == 0) {
            #pragma unroll
            for (int c = 0; c < 4; ++c) {
                mbar_expect(hbar0 + c * 8, 32768);
                bulk_g2s(smem_u32(hsm) + c * 32768, g_zH + c * 8192, 32768, hbar0 + c * 8);
            }
        }

        ull acc[12];
        if (active) {
            #pragma unroll
            for (int j = 0; j < 12; ++j) acc[j] = 0ULL;
            // x part first (gate blocks): prefetched last step.
            if (!isOut) {
                mbar_wait(xbar, xph);
                const float* zp = xsm + (wid * 16) * 64 + lane * 2;
                const ulonglong2* wp = (const ulonglong2*)(wsm + (size_t)(wid * 80 + 64) * 12);
                #pragma unroll 4
                for (int i = 0; i < 16; ++i) {
                    ull z = *(const ull*)(zp + i * 64);
                    ulonglong2 w0 = wp[i*6+0], w1 = wp[i*6+1], w2 = wp[i*6+2];
                    acc[0] = ffma2(z, w0.x, acc[0]);  acc[1] = ffma2(z, w0.y, acc[1]);
                    acc[2] = ffma2(z, w1.x, acc[2]);  acc[3] = ffma2(z, w1.y, acc[3]);
                    acc[4] = ffma2(z, w2.x, acc[4]);  acc[5] = ffma2(z, w2.y, acc[5]);
                    ulonglong2 w3 = wp[i*6+3], w4 = wp[i*6+4], w5 = wp[i*6+5];
                    acc[6] = ffma2(z, w3.x, acc[6]);   acc[7]  = ffma2(z, w3.y, acc[7]);
                    acc[8] = ffma2(z, w4.x, acc[8]);   acc[9]  = ffma2(z, w4.y, acc[9]);
                    acc[10] = ffma2(z, w5.x, acc[10]); acc[11] = ffma2(z, w5.y, acc[11]);
                }
            }
            // h part: wait only this warp-pair's slice.
            mbar_wait(hbar0 + (wid >> 1) * 8, hph);
            const float* zp = hsm + (wid * 64) * 64 + lane * 2;
            const ulonglong2* wp = (const ulonglong2*)(wsm + (size_t)(wid * 80) * 12);
            #pragma unroll 4
            for (int i = 0; i < 64; ++i) {
                ull z = *(const ull*)(zp + i * 64);
                ulonglong2 w0 = wp[i*6+0], w1 = wp[i*6+1], w2 = wp[i*6+2];
                acc[0] = ffma2(z, w0.x, acc[0]);  acc[1] = ffma2(z, w0.y, acc[1]);
                acc[2] = ffma2(z, w1.x, acc[2]);  acc[3] = ffma2(z, w1.y, acc[3]);
                acc[4] = ffma2(z, w2.x, acc[4]);  acc[5] = ffma2(z, w2.y, acc[5]);
                ulonglong2 w3 = wp[i*6+3], w4 = wp[i*6+4], w5 = wp[i*6+5];
                acc[6] = ffma2(z, w3.x, acc[6]);   acc[7]  = ffma2(z, w3.y, acc[7]);
                acc[8] = ffma2(z, w4.x, acc[8]);   acc[9]  = ffma2(z, w4.y, acc[9]);
                acc[10] = ffma2(z, w5.x, acc[10]); acc[11] = ffma2(z, w5.y, acc[11]);
            }
        }
        __syncthreads();   // all warps done reading hsm/xsm before redsm / x-prefetch

        // Prefetch x(u+1) (gate blocks) — overlaps reduce/elementwise/barrier.
        if (!isOut && (u + 1) < TSTEPS && tid == 0) {
            mbar_expect(xbar, 32768);
            bulk_g2s(smem_u32(xsm), g_xT + (size_t)(u + 1) * 8192, 32768, xbar);
        }

        if (active) {
            #pragma unroll
            for (int j = 0; j < 12; ++j)
                redsm[(wid * 12 + j) * 32 + lane] = acc[j];
        }
        __syncthreads();

        if (active) {
            if (isOut) {
                // outputs for step u-1; thread covers 3 (col,b) cells
                #pragma unroll
                for (int q = 0; q < 3; ++q) {
                    int cix = tid + q * 256;
                    int j = cix >> 6, b = cix & 63;
                    int oc = oc0 + j;
                    if (oc < OO) {
                        float s = 0.f;
                        #pragma unroll
                        for (int w = 0; w < 8; ++w)
                            s += redf[((w * 12 + j) * 32 + (b >> 1)) * 2 + (b & 1)];
                        out[((size_t)(u - 1) * BB + b) * OO + oc] = s + b_out[oc];
                    }
                }
            } else {
                // fused reduce + elementwise for (h0+eh, eb)
                float pi = rbi, po = rbo, pc = rbc;
                int bhalf = (eb >> 1) * 2 + (eb & 1);
                #pragma unroll
                for (int w = 0; w < 8; ++w) {
                    int base = ((w * 12 + eh * 3) * 32) * 2 + bhalf;
                    pi += redf[base];
                    po += redf[base + 64];
                    pc += redf[base + 128];
                }
                float iv = sigm(pi);
                float ov = sigm(po);
                float gv = tanhf(pc);
                int h = h0 + eh;
                // lag from register shift-ring (values identical to gmem ring)
                float l0 = 0.f, l1 = 0.f, l2 = 0.f, l3 = 0.f;
                #pragma unroll
                for (int j = 0; j < KK; j += 4) {
                    l0 += wd_sm[eh * KK + j    ] * rv[j];
                    l1 += wd_sm[eh * KK + j + 1] * rv[j + 1];
                    l2 += wd_sm[eh * KK + j + 2] * rv[j + 2];
                    l3 += wd_sm[eh * KK + j + 3] * rv[j + 3];
                }
                float cc = iv * gv - ((l0 + l1) + (l2 + l3));
                float hn = ov * tanhf(cc);
                #pragma unroll
                for (int j = 0; j < KK - 1; ++j) rv[j] = rv[j + 1];
                rv[KK - 1] = cc;
                // gmem ring only for the last 32 steps (all hc_last needs);
                // slot u-480 == (480+j) layout -> epilogue unchanged.
                if (u >= TSTEPS - KK)
                    g_ring[((u - (TSTEPS - KK)) << 15) + h * 64 + eb] = cc;
                g_zH[h * 64 + eb] = hn;
                if (u == TSTEPS - 1)
                    out[(size_t)TSTEPS * BB * OO + (size_t)eb * HH + h] = hn;  // h_last
                xph ^= 1;
            }
            hph ^= 1;
        }
        gridbar(barid++);
    }

    // hc_last[j][b][h]: slot j holds c_{480+j}
    const size_t OFF_HC = (size_t)TSTEPS * BB * OO + (size_t)BB * HH;
    for (int idx = gtid; idx < KK * BB * HH; idx += GT) {
        int j = idx >> 15;
        int r = idx & 32767;
        int b = r >> 9, h = r & 511;
        out[OFF_HC + idx] = __ldcg(&g_ring[((size_t)j << 15) + h * 64 + b]);
    }
}

extern "C" void kernel_launch(void* const* d_in, const int* in_sizes, int n_in,
                              void* d_out, int out_size) {
    (void)in_sizes; (void)n_in; (void)out_size;
    const float* inputs   = (const float*)d_in[0];
    const float* W_i      = (const float*)d_in[1];
    const float* b_i      = (const float*)d_in[2];
    const float* W_o      = (const float*)d_in[3];
    const float* b_o      = (const float*)d_in[4];
    const float* W_c      = (const float*)d_in[5];
    const float* b_c      = (const float*)d_in[6];
    const float* W_out    = (const float*)d_in[7];
    const float* b_out    = (const float*)d_in[8];
    const float* d_values = (const float*)d_in[9];
    float* out = (float*)d_out;

    cudaFuncSetAttribute(mlstm_kernel, cudaFuncAttributeMaxDynamicSharedMemorySize, SMEM_BYTES);
    mlstm_kernel<<<NBLK, NTH, SMEM_BYTES>>>(inputs, W_i, b_i, W_o, b_o, W_c, b_c,
                                            W_out, b_out, d_values, out);
}

// round 14
// speedup vs baseline: 1.4439x; 1.1924x over previous
#include <cuda_runtime.h>
#include <cuda_bf16.h>
#include <cstdint>

// Problem constants
#define TSTEPS 512
#define BB 64
#define II 128
#define HH 512
#define OO 128
#define KK 32
#define ZK 640                  // I + H
#define NBLK 139                // 128 gate blocks + 11 out blocks
#define NTH 256
#define GT (NBLK*NTH)

// smem layout (bytes)
#define HSM_OFF   0             // h slice [512][64] f32 = 131072
#define XSM_OFF   131072        // x slice [128][64] f32 = 32768
#define WSM_OFF   163840        // weights k-paired [320][12] ull = 30720
#define WD_OFF    194560        // frac-diff weights [4][32] f32 = 512
#define MBAR_OFF  195072        // 4 h mbars + 1 x mbar (8B each)
#define SMEM_BYTES (MBAR_OFF + 64)

typedef unsigned long long ull;

// ------------- static device scratch (no allocations) -------------
__device__ float g_xT[TSTEPS*II*BB];     // inputs transposed: [t][k][b]
__device__ float g_zH[HH*BB];            // h_{t-1}: [h][b]
__device__ float g_ring[KK*HH*BB];       // last 32 cell states: [j][h][b]
__device__ unsigned g_cnt;
__device__ volatile unsigned g_sense_v;

// ------------- helpers -------------
__device__ __forceinline__ ull ffma2(ull a, ull b, ull c) {
    ull d;
    asm("fma.rn.f32x2 %0, %1, %2, %3;" : "=l"(d) : "l"(a), "l"(b), "l"(c));
    return d;
}
__device__ __forceinline__ ull pack2(float lo, float hi) {
    ull r;
    asm("mov.b64 %0, {%1, %2};" : "=l"(r) : "f"(lo), "f"(hi));
    return r;
}
__device__ __forceinline__ ull pack2w(float lo, float hi) {   // host-of-init variant
    ull r;
    asm("mov.b64 %0, {%1, %2};" : "=l"(r) : "f"(lo), "f"(hi));
    return r;
}
__device__ __forceinline__ float lo32(ull v) { return __uint_as_float((unsigned)v); }
__device__ __forceinline__ float hi32(ull v) { return __uint_as_float((unsigned)(v >> 32)); }
__device__ __forceinline__ float sigm(float x) { return 1.f / (1.f + __expf(-x)); }

__device__ __forceinline__ unsigned smem_u32(const void* p) {
    return (unsigned)__cvta_generic_to_shared(p);
}
__device__ __forceinline__ void mbar_init(unsigned mbar, unsigned cnt) {
    asm volatile("mbarrier.init.shared.b64 [%0], %1;" :: "r"(mbar), "r"(cnt) : "memory");
}
__device__ __forceinline__ void mbar_expect(unsigned mbar, unsigned bytes) {
    asm volatile("mbarrier.arrive.expect_tx.shared.b64 _, [%0], %1;"
                 :: "r"(mbar), "r"(bytes) : "memory");
}
__device__ __forceinline__ void bulk_g2s(unsigned dst, const void* src,
                                         unsigned bytes, unsigned mbar) {
    asm volatile("cp.async.bulk.shared::cluster.global.mbarrier::complete_tx::bytes "
                 "[%0], [%1], %2, [%3];"
                 :: "r"(dst), "l"(src), "r"(bytes), "r"(mbar) : "memory");
}
__device__ __forceinline__ void mbar_wait(unsigned mbar, unsigned parity) {
    asm volatile(
        "{\n\t"
        ".reg .pred P;\n\t"
        "WAIT_%=:\n\t"
        "mbarrier.try_wait.parity.acquire.cta.shared::cta.b64 P, [%0], %1, 0x989680;\n\t"
        "@P bra.uni DONE_%=;\n\t"
        "bra.uni WAIT_%=;\n\t"
        "DONE_%=:\n\t"
        "}" :: "r"(mbar), "r"(parity) : "memory");
}

// Champion serial sense-reversing grid barrier; state self-restores (even calls).
__device__ __forceinline__ void gridbar(unsigned n) {
    __threadfence();
    __syncthreads();
    if (threadIdx.x == 0) {
        unsigned s = (~n) & 1u;
        if (atomicAdd(&g_cnt, 1u) == NBLK - 1) {
            g_cnt = 0;
            __threadfence();
            g_sense_v = s;
        } else {
            while (g_sense_v != s) __nanosleep(16);
        }
    }
    __syncthreads();
}

extern __shared__ char smem_raw[];

__global__ void __launch_bounds__(NTH, 1)
mlstm_kernel(const float* __restrict__ inputs,
             const float* __restrict__ W_i, const float* __restrict__ b_i,
             const float* __restrict__ W_o, const float* __restrict__ b_o,
             const float* __restrict__ W_c, const float* __restrict__ b_c,
             const float* __restrict__ W_out, const float* __restrict__ b_out,
             const float* __restrict__ d_values,
             float* __restrict__ out)
{
    float* hsm   = (float*)(smem_raw + HSM_OFF);    // [512][64]
    float* xsm   = (float*)(smem_raw + XSM_OFF);    // [128][64]
    ull*   wsm   = (ull*)(smem_raw + WSM_OFF);      // [320 kpairs][12], warp-major
    float* wd_sm = (float*)(smem_raw + WD_OFF);     // [4][32]
    ull*   redsm = (ull*)(smem_raw + HSM_OFF);      // reuse h region: [8][12][64] ull

    const unsigned hbar0 = smem_u32(smem_raw + MBAR_OFF);  // 4 mbars, 8B apart
    const unsigned xbar  = hbar0 + 32;

    const int tid  = threadIdx.x;
    const int blk  = blockIdx.x;
    const int gtid = blk * NTH + tid;
    const int lane = tid & 31;
    const int wid  = tid >> 5;

    const bool isOut = (blk >= 128);
    const int h0  = blk * 4;                 // gate blocks: 4 h each
    const int oc0 = (blk - 128) * 12;        // out blocks
    const int eh  = tid >> 6;                // elementwise hh (0..3)
    const int eb  = tid & 63;                // elementwise b

    // ---------------- init ----------------
    if (tid == 0) {
        for (int c = 0; c < 4; ++c) mbar_init(hbar0 + c * 8, 1);
        mbar_init(xbar, 1);
    }
    // Weights -> smem, k-PAIRED (no duplication): storage pair index kp for
    // warp w, p = kp - w*40: p<32 -> h rows k0 = 128+w*64+2p; p>=32 -> x rows
    // k0 = w*16 + 2*(p-32). wsm[kp*12+j] = (W[k0][col], W[k0+1][col]).
    for (int idx = tid; idx < 320 * 12; idx += NTH) {
        int kp = idx / 12;
        int j  = idx - kp * 12;
        int w  = kp / 40, p = kp - w * 40;
        int k0 = (p < 32) ? (128 + w * 64 + 2 * p) : (w * 16 + 2 * (p - 32));
        float wv0 = 0.f, wv1 = 0.f;
        if (!isOut) {
            int hh = j / 3, g = j - hh * 3;
            const float* W = (g == 0) ? W_i : (g == 1) ? W_o : W_c;
            wv0 = W[k0 * HH + h0 + hh];
            wv1 = W[(k0 + 1) * HH + h0 + hh];
        } else if ((oc0 + j) < OO && k0 >= II) {
            wv0 = W_out[(k0 - II) * OO + oc0 + j];
            wv1 = W_out[(k0 + 1 - II) * OO + oc0 + j];
        }
        wsm[idx] = pack2w(wv0, wv1);
    }
    float rbi = 0.f, rbo = 0.f, rbc = 0.f;
    if (!isOut) {
        if (tid < 4) {
            float dv = 0.5f * sigm(d_values[h0 + tid]);
            float v = 1.f;
            for (int i = 0; i < KK; ++i) {
                v = v * ((float)i - dv) / ((float)i + 1.f);
                wd_sm[tid * KK + (KK - 1 - i)] = v;
            }
        }
        rbi = b_i[h0 + eh]; rbo = b_o[h0 + eh]; rbc = b_c[h0 + eh];
    }
    // Transpose inputs once: g_xT[t][k][b]
    for (int idx = gtid; idx < TSTEPS * II * BB; idx += GT) {
        int t = idx >> 13;
        int r = idx & 8191;
        int k = r & 127, b = r >> 7;
        g_xT[(size_t)t * 8192 + k * 64 + b] = inputs[((size_t)t * BB + b) * II + k];
    }
    for (int idx = gtid; idx < HH * BB; idx += GT) g_zH[idx] = 0.f;
    for (int idx = gtid; idx < KK * HH * BB; idx += GT) g_ring[idx] = 0.f;
    __syncthreads();
    unsigned barid = 0;
    gridbar(barid++);

    // Prefetch x(0) (gate blocks only)
    if (!isOut && tid == 0) {
        mbar_expect(xbar, 32768);
        bulk_g2s(smem_u32(xsm), g_xT, 32768, xbar);
    }

    unsigned hph = 0, xph = 0;
    float rv[KK];                 // register shift-ring: rv[j] = c_{u-32+j}
    #pragma unroll
    for (int j = 0; j < KK; ++j) rv[j] = 0.f;

    // ---------------- main scan ----------------
    for (int u = 0; u <= TSTEPS; ++u) {
        const bool active = isOut ? (u >= 1) : (u < TSTEPS);

        // h DMA: each CTA pulls all four 32KB slices itself (champion pattern).
        if (active && tid == 0) {
            #pragma unroll
            for (int c = 0; c < 4; ++c) {
                mbar_expect(hbar0 + c * 8, 32768);
                bulk_g2s(smem_u32(hsm) + c * 32768, g_zH + c * 8192, 32768, hbar0 + c * 8);
            }
        }

        ull accA[12], accB[12];     // accA: b=lane, accB: b=lane+32; halves = (k even, k odd)
        if (active) {
            #pragma unroll
            for (int j = 0; j < 12; ++j) { accA[j] = 0ULL; accB[j] = 0ULL; }
            // x part first (gate blocks): 8 k-pairs, prefetched last step.
            if (!isOut) {
                mbar_wait(xbar, xph);
                const float* zr = xsm + (wid * 16) * 64 + lane;
                const ulonglong2* wp = (const ulonglong2*)(wsm + (size_t)(wid * 40 + 32) * 12);
                #pragma unroll
                for (int p = 0; p < 8; ++p) {
                    float a0 = zr[(2*p)*64],      a1 = zr[(2*p+1)*64];
                    float c0 = zr[(2*p)*64 + 32], c1 = zr[(2*p+1)*64 + 32];
                    ull zA = pack2(a0, a1), zB = pack2(c0, c1);
                    ulonglong2 w0 = wp[p*6+0], w1 = wp[p*6+1], w2 = wp[p*6+2];
                    accA[0] = ffma2(zA, w0.x, accA[0]);  accB[0] = ffma2(zB, w0.x, accB[0]);
                    accA[1] = ffma2(zA, w0.y, accA[1]);  accB[1] = ffma2(zB, w0.y, accB[1]);
                    accA[2] = ffma2(zA, w1.x, accA[2]);  accB[2] = ffma2(zB, w1.x, accB[2]);
                    accA[3] = ffma2(zA, w1.y, accA[3]);  accB[3] = ffma2(zB, w1.y, accB[3]);
                    accA[4] = ffma2(zA, w2.x, accA[4]);  accB[4] = ffma2(zB, w2.x, accB[4]);
                    accA[5] = ffma2(zA, w2.y, accA[5]);  accB[5] = ffma2(zB, w2.y, accB[5]);
                    ulonglong2 w3 = wp[p*6+3], w4 = wp[p*6+4], w5 = wp[p*6+5];
                    accA[6] = ffma2(zA, w3.x, accA[6]);   accB[6]  = ffma2(zB, w3.x, accB[6]);
                    accA[7] = ffma2(zA, w3.y, accA[7]);   accB[7]  = ffma2(zB, w3.y, accB[7]);
                    accA[8] = ffma2(zA, w4.x, accA[8]);   accB[8]  = ffma2(zB, w4.x, accB[8]);
                    accA[9] = ffma2(zA, w4.y, accA[9]);   accB[9]  = ffma2(zB, w4.y, accB[9]);
                    accA[10] = ffma2(zA, w5.x, accA[10]); accB[10] = ffma2(zB, w5.x, accB[10]);
                    accA[11] = ffma2(zA, w5.y, accA[11]); accB[11] = ffma2(zB, w5.y, accB[11]);
                }
            }
            // h part: 32 k-pairs; wait only this warp-pair's slice.
            mbar_wait(hbar0 + (wid >> 1) * 8, hph);
            {
                const float* zr = hsm + (wid * 64) * 64 + lane;
                const ulonglong2* wp = (const ulonglong2*)(wsm + (size_t)(wid * 40) * 12);
                #pragma unroll 4
                for (int p = 0; p < 32; ++p) {
                    float a0 = zr[(2*p)*64],      a1 = zr[(2*p+1)*64];
                    float c0 = zr[(2*p)*64 + 32], c1 = zr[(2*p+1)*64 + 32];
                    ull zA = pack2(a0, a1), zB = pack2(c0, c1);
                    ulonglong2 w0 = wp[p*6+0], w1 = wp[p*6+1], w2 = wp[p*6+2];
                    accA[0] = ffma2(zA, w0.x, accA[0]);  accB[0] = ffma2(zB, w0.x, accB[0]);
                    accA[1] = ffma2(zA, w0.y, accA[1]);  accB[1] = ffma2(zB, w0.y, accB[1]);
                    accA[2] = ffma2(zA, w1.x, accA[2]);  accB[2] = ffma2(zB, w1.x, accB[2]);
                    accA[3] = ffma2(zA, w1.y, accA[3]);  accB[3] = ffma2(zB, w1.y, accB[3]);
                    accA[4] = ffma2(zA, w2.x, accA[4]);  accB[4] = ffma2(zB, w2.x, accB[4]);
                    accA[5] = ffma2(zA, w2.y, accA[5]);  accB[5] = ffma2(zB, w2.y, accB[5]);
                    ulonglong2 w3 = wp[p*6+3], w4 = wp[p*6+4], w5 = wp[p*6+5];
                    accA[6] = ffma2(zA, w3.x, accA[6]);   accB[6]  = ffma2(zB, w3.x, accB[6]);
                    accA[7] = ffma2(zA, w3.y, accA[7]);   accB[7]  = ffma2(zB, w3.y, accB[7]);
                    accA[8] = ffma2(zA, w4.x, accA[8]);   accB[8]  = ffma2(zB, w4.x, accB[8]);
                    accA[9] = ffma2(zA, w4.y, accA[9]);   accB[9]  = ffma2(zB, w4.y, accB[9]);
                    accA[10] = ffma2(zA, w5.x, accA[10]); accB[10] = ffma2(zB, w5.x, accB[10]);
                    accA[11] = ffma2(zA, w5.y, accA[11]); accB[11] = ffma2(zB, w5.y, accB[11]);
                }
            }
        }
        __syncthreads();   // all warps done reading hsm/xsm before redsm / x-prefetch

        // Prefetch x(u+1) (gate blocks) — overlaps reduce/elementwise/barrier.
        if (!isOut && (u + 1) < TSTEPS && tid == 0) {
            mbar_expect(xbar, 32768);
            bulk_g2s(smem_u32(xsm), g_xT + (size_t)(u + 1) * 8192, 32768, xbar);
        }

        if (active) {
            #pragma unroll
            for (int j = 0; j < 12; ++j) {
                redsm[(wid * 12 + j) * 64 + lane]      = accA[j];
                redsm[(wid * 12 + j) * 64 + lane + 32] = accB[j];
            }
        }
        __syncthreads();

        if (active) {
            if (isOut) {
                // outputs for step u-1; thread covers 3 (col,b) cells
                #pragma unroll
                for (int q = 0; q < 3; ++q) {
                    int cix = tid + q * 256;
                    int j = cix >> 6, b = cix & 63;
                    int oc = oc0 + j;
                    if (oc < OO) {
                        float s = 0.f;
                        #pragma unroll
                        for (int w = 0; w < 8; ++w) {
                            ull v = redsm[(w * 12 + j) * 64 + b];
                            s += lo32(v) + hi32(v);
                        }
                        out[((size_t)(u - 1) * BB + b) * OO + oc] = s + b_out[oc];
                    }
                }
            } else {
                // fused reduce + elementwise for (h0+eh, eb)
                float pi = rbi, po = rbo, pc = rbc;
                #pragma unroll
                for (int w = 0; w < 8; ++w) {
                    int base = (w * 12 + eh * 3) * 64 + eb;
                    ull v0 = redsm[base];
                    ull v1 = redsm[base + 64];
                    ull v2 = redsm[base + 128];
                    pi += lo32(v0) + hi32(v0);
                    po += lo32(v1) + hi32(v1);
                    pc += lo32(v2) + hi32(v2);
                }
                float iv = sigm(pi);
                float ov = sigm(po);
                float gv = tanhf(pc);
                int h = h0 + eh;
                // lag from register shift-ring
                float l0 = 0.f, l1 = 0.f, l2 = 0.f, l3 = 0.f;
                #pragma unroll
                for (int j = 0; j < KK; j += 4) {
                    l0 += wd_sm[eh * KK + j    ] * rv[j];
                    l1 += wd_sm[eh * KK + j + 1] * rv[j + 1];
                    l2 += wd_sm[eh * KK + j + 2] * rv[j + 2];
                    l3 += wd_sm[eh * KK + j + 3] * rv[j + 3];
                }
                float cc = iv * gv - ((l0 + l1) + (l2 + l3));
                float hn = ov * tanhf(cc);
                #pragma unroll
                for (int j = 0; j < KK - 1; ++j) rv[j] = rv[j + 1];
                rv[KK - 1] = cc;
                // gmem ring only for the last 32 steps (all hc_last needs)
                if (u >= TSTEPS - KK)
                    g_ring[((u - (TSTEPS - KK)) << 15) + h * 64 + eb] = cc;
                g_zH[h * 64 + eb] = hn;
                if (u == TSTEPS - 1)
                    out[(size_t)TSTEPS * BB * OO + (size_t)eb * HH + h] = hn;  // h_last
                xph ^= 1;
            }
            hph ^= 1;
        }
        gridbar(barid++);
    }

    // hc_last[j][b][h]: slot j holds c_{480+j}
    const size_t OFF_HC = (size_t)TSTEPS * BB * OO + (size_t)BB * HH;
    for (int idx = gtid; idx < KK * BB * HH; idx += GT) {
        int j = idx >> 15;
        int r = idx & 32767;
        int b = r >> 9, h = r & 511;
        out[OFF_HC + idx] = __ldcg(&g_ring[((size_t)j << 15) + h * 64 + b]);
    }
}

extern "C" void kernel_launch(void* const* d_in, const int* in_sizes, int n_in,
                              void* d_out, int out_size) {
    (void)in_sizes; (void)n_in; (void)out_size;
    const float* inputs   = (const float*)d_in[0];
    const float* W_i      = (const float*)d_in[1];
    const float* b_i      = (const float*)d_in[2];
    const float* W_o      = (const float*)d_in[3];
    const float* b_o      = (const float*)d_in[4];
    const float* W_c      = (const float*)d_in[5];
    const float* b_c      = (const float*)d_in[6];
    const float* W_out    = (const float*)d_in[7];
    const float* b_out    = (const float*)d_in[8];
    const float* d_values = (const float*)d_in[9];
    float* out = (float*)d_out;

    cudaFuncSetAttribute(mlstm_kernel, cudaFuncAttributeMaxDynamicSharedMemorySize, SMEM_BYTES);
    mlstm_kernel<<<NBLK, NTH, SMEM_BYTES>>>(inputs, W_i, b_i, W_o, b_o, W_c, b_c,
                                            W_out, b_out, d_values, out);
}